// round 1
// baseline (speedup 1.0000x reference)
#include <cuda_runtime.h>
#include <cstdint>
#include <math.h>

// ---------------------------------------------------------------------------
// GCNGraph: h = relu(adj @ (x @ W1) + b1); h = relu(adj @ (h @ W2) + b2);
//           h = adj @ (h @ W3) + b3; g = segment_mean(h); MLP tail -> sigmoid.
// Strategy: TF32 mma.sync GEMMs (fp32 accumulate), fused bias/relu epilogue.
// ---------------------------------------------------------------------------

#define NN      8192
#define HF      512
#define GRAPHS  64

#define BM 128
#define BN 128
#define BK 16
#define NTHREADS 256

// scratch (no allocations allowed)
__device__ float g_bufA[NN * HF];
__device__ float g_bufB[NN * HF];
__device__ float g_sums[GRAPHS * HF];

__device__ __forceinline__ uint32_t f2tf32(float x) {
    uint32_t r;
    asm("cvt.rna.tf32.f32 %0, %1;" : "=r"(r) : "f"(x));
    return r;
}

__device__ __forceinline__ void mma_tf32(float* c, const uint32_t* a, const uint32_t* b) {
    asm volatile(
        "mma.sync.aligned.m16n8k8.row.col.f32.tf32.tf32.f32 "
        "{%0,%1,%2,%3}, {%4,%5,%6,%7}, {%8,%9}, {%0,%1,%2,%3};"
        : "+f"(c[0]), "+f"(c[1]), "+f"(c[2]), "+f"(c[3])
        : "r"(a[0]), "r"(a[1]), "r"(a[2]), "r"(a[3]),
          "r"(b[0]), "r"(b[1]));
}

// C[M,N] = A[M,K] @ B[K,N] (+bias over N)(, relu). All row-major fp32.
// M % 128 == 0, N % 128 == 0, K % 16 == 0.
template <bool RELU, bool BIAS>
__global__ void __launch_bounds__(NTHREADS)
gemm_tf32(const float* __restrict__ A, const float* __restrict__ B,
          float* __restrict__ C, const float* __restrict__ bias,
          int M, int N, int K)
{
    __shared__ uint32_t As[2][BM][BK + 4];   // pad 4: conflict-free frag loads
    __shared__ uint32_t Bs[2][BK][BN + 4];

    const int bm = blockIdx.y * BM;
    const int bn = blockIdx.x * BN;
    const int tid  = threadIdx.x;
    const int warp = tid >> 5;
    const int lane = tid & 31;
    const int wm = (warp >> 2) * 64;   // warp m-offset: 0 or 64
    const int wn = (warp & 3) * 32;    // warp n-offset: 0..96
    const int g  = lane >> 2;          // groupID
    const int q  = lane & 3;           // thread-in-group

    float acc[4][4][4];
#pragma unroll
    for (int i = 0; i < 4; i++)
#pragma unroll
        for (int j = 0; j < 4; j++)
#pragma unroll
            for (int r = 0; r < 4; r++) acc[i][j][r] = 0.f;

    // global->smem mapping
    const int arow = tid >> 2;            // 0..63 (two passes: +0, +64)
    const int acol = (tid & 3) * 4;       // 0,4,8,12
    const int brow = tid >> 5;            // 0..7  (two passes: +0, +8)
    const int bcol = (tid & 31) * 4;      // 0..124

    const int nk = K / BK;

    float4 ra0, ra1, rb0, rb1;

    // prologue: fetch k-block 0
    ra0 = *(const float4*)(A + (size_t)(bm + arow) * K + acol);
    ra1 = *(const float4*)(A + (size_t)(bm + arow + 64) * K + acol);
    rb0 = *(const float4*)(B + (size_t)(brow) * N + bn + bcol);
    rb1 = *(const float4*)(B + (size_t)(brow + 8) * N + bn + bcol);
    {
        uint4 u;
        u.x = f2tf32(ra0.x); u.y = f2tf32(ra0.y); u.z = f2tf32(ra0.z); u.w = f2tf32(ra0.w);
        *(uint4*)&As[0][arow][acol] = u;
        u.x = f2tf32(ra1.x); u.y = f2tf32(ra1.y); u.z = f2tf32(ra1.z); u.w = f2tf32(ra1.w);
        *(uint4*)&As[0][arow + 64][acol] = u;
        u.x = f2tf32(rb0.x); u.y = f2tf32(rb0.y); u.z = f2tf32(rb0.z); u.w = f2tf32(rb0.w);
        *(uint4*)&Bs[0][brow][bcol] = u;
        u.x = f2tf32(rb1.x); u.y = f2tf32(rb1.y); u.z = f2tf32(rb1.z); u.w = f2tf32(rb1.w);
        *(uint4*)&Bs[0][brow + 8][bcol] = u;
    }
    __syncthreads();

    for (int t = 0; t < nk; t++) {
        const int cur = t & 1;
        const int nxt = cur ^ 1;
        const bool more = (t + 1 < nk);
        if (more) {
            const int k0 = (t + 1) * BK;
            ra0 = *(const float4*)(A + (size_t)(bm + arow) * K + k0 + acol);
            ra1 = *(const float4*)(A + (size_t)(bm + arow + 64) * K + k0 + acol);
            rb0 = *(const float4*)(B + (size_t)(k0 + brow) * N + bn + bcol);
            rb1 = *(const float4*)(B + (size_t)(k0 + brow + 8) * N + bn + bcol);
        }

#pragma unroll
        for (int kk = 0; kk < BK; kk += 8) {
            uint32_t af[4][4], bf[4][2];
#pragma unroll
            for (int i = 0; i < 4; i++) {
                const int r0 = wm + i * 16 + g;
                af[i][0] = As[cur][r0][kk + q];
                af[i][1] = As[cur][r0 + 8][kk + q];
                af[i][2] = As[cur][r0][kk + q + 4];
                af[i][3] = As[cur][r0 + 8][kk + q + 4];
            }
#pragma unroll
            for (int j = 0; j < 4; j++) {
                const int c0 = wn + j * 8 + g;
                bf[j][0] = Bs[cur][kk + q][c0];
                bf[j][1] = Bs[cur][kk + q + 4][c0];
            }
#pragma unroll
            for (int i = 0; i < 4; i++)
#pragma unroll
                for (int j = 0; j < 4; j++)
                    mma_tf32(acc[i][j], af[i], bf[j]);
        }

        if (more) {
            uint4 u;
            u.x = f2tf32(ra0.x); u.y = f2tf32(ra0.y); u.z = f2tf32(ra0.z); u.w = f2tf32(ra0.w);
            *(uint4*)&As[nxt][arow][acol] = u;
            u.x = f2tf32(ra1.x); u.y = f2tf32(ra1.y); u.z = f2tf32(ra1.z); u.w = f2tf32(ra1.w);
            *(uint4*)&As[nxt][arow + 64][acol] = u;
            u.x = f2tf32(rb0.x); u.y = f2tf32(rb0.y); u.z = f2tf32(rb0.z); u.w = f2tf32(rb0.w);
            *(uint4*)&Bs[nxt][brow][bcol] = u;
            u.x = f2tf32(rb1.x); u.y = f2tf32(rb1.y); u.z = f2tf32(rb1.z); u.w = f2tf32(rb1.w);
            *(uint4*)&Bs[nxt][brow + 8][bcol] = u;
        }
        __syncthreads();
    }

    // epilogue
#pragma unroll
    for (int i = 0; i < 4; i++) {
#pragma unroll
        for (int j = 0; j < 4; j++) {
            const int row = bm + wm + i * 16 + g;
            const int col = bn + wn + j * 8 + 2 * q;
            float bv0 = 0.f, bv1 = 0.f;
            if (BIAS) { bv0 = bias[col]; bv1 = bias[col + 1]; }
            float v0 = acc[i][j][0] + bv0;
            float v1 = acc[i][j][1] + bv1;
            float v2 = acc[i][j][2] + bv0;
            float v3 = acc[i][j][3] + bv1;
            if (RELU) {
                v0 = fmaxf(v0, 0.f); v1 = fmaxf(v1, 0.f);
                v2 = fmaxf(v2, 0.f); v3 = fmaxf(v3, 0.f);
            }
            *(float2*)(C + (size_t)row * N + col)       = make_float2(v0, v1);
            *(float2*)(C + (size_t)(row + 8) * N + col) = make_float2(v2, v3);
        }
    }
}

__global__ void zero_sums(float* __restrict__ s) {
    s[blockIdx.x * blockDim.x + threadIdx.x] = 0.f;
}

// segment-sum: segment_ids are sorted, so run-length accumulate in registers.
// grid: (8 feat-chunks, 16 node-chunks), 64 threads.
__global__ void readout(const float* __restrict__ H, const int* __restrict__ seg,
                        float* __restrict__ sums)
{
    const int f  = blockIdx.x * 64 + threadIdx.x;
    const int n0 = blockIdx.y * 512;
    const int n1 = n0 + 512;
    float acc = 0.f;
    int cur = seg[n0];
    for (int n = n0; n < n1; n++) {
        const int s = seg[n];
        if (s != cur) {
            atomicAdd(&sums[cur * HF + f], acc);
            acc = 0.f;
            cur = s;
        }
        acc += H[(size_t)n * HF + f];
    }
    atomicAdd(&sums[cur * HF + f], acc);
}

// fused: per-graph mean + MLP (512->16->8->1) + sigmoid. single block, 1024 thr.
__global__ void mlp_tail(const float* __restrict__ sums, const int* __restrict__ seg,
                         const float* __restrict__ D1, const float* __restrict__ db1,
                         const float* __restrict__ D2, const float* __restrict__ db2,
                         const float* __restrict__ D3, const float* __restrict__ db3,
                         float* __restrict__ out)
{
    __shared__ int   cnt[GRAPHS];
    __shared__ float s1[GRAPHS][16];
    __shared__ float s2[GRAPHS][8];
    const int tid = threadIdx.x;

    if (tid < GRAPHS) cnt[tid] = 0;
    __syncthreads();
    for (int n = tid; n < NN; n += 1024) atomicAdd(&cnt[seg[n]], 1);
    __syncthreads();

    {   // stage 1: [64,512] @ [512,16]
        const int gph = tid >> 4, j = tid & 15;
        float acc = 0.f;
        const float* srow = sums + gph * HF;
        for (int k = 0; k < HF; k++) acc += srow[k] * D1[k * 16 + j];
        const float c = (float)max(cnt[gph], 1);
        s1[gph][j] = fmaxf(acc / c + db1[j], 0.f);
    }
    __syncthreads();
    if (tid < 512) {  // stage 2: [64,16] @ [16,8]
        const int gph = tid >> 3, j = tid & 7;
        float acc = 0.f;
        for (int k = 0; k < 16; k++) acc += s1[gph][k] * D2[k * 8 + j];
        s2[gph][j] = fmaxf(acc + db2[j], 0.f);
    }
    __syncthreads();
    if (tid < GRAPHS) {  // stage 3: [64,8] @ [8,1] -> sigmoid
        float acc = 0.f;
        for (int k = 0; k < 8; k++) acc += s2[tid][k] * D3[k];
        out[tid] = 1.f / (1.f + expf(-(acc + db3[0])));
    }
}

extern "C" void kernel_launch(void* const* d_in, const int* in_sizes, int n_in,
                              void* d_out, int out_size)
{
    const float* X   = (const float*)d_in[0];   // [8192, 256]
    const float* adj = (const float*)d_in[1];   // [8192*8192]
    const int*   seg = (const int*)d_in[2];     // [8192]
    // num_graphs scalar may or may not be materialized as an input
    const int base = n_in - 12;                 // 16 inputs -> 4, 15 -> 3
    const float* W1  = (const float*)d_in[base + 0];
    const float* b1  = (const float*)d_in[base + 1];
    const float* W2  = (const float*)d_in[base + 2];
    const float* b2  = (const float*)d_in[base + 3];
    const float* W3  = (const float*)d_in[base + 4];
    const float* b3  = (const float*)d_in[base + 5];
    const float* D1  = (const float*)d_in[base + 6];
    const float* db1 = (const float*)d_in[base + 7];
    const float* D2  = (const float*)d_in[base + 8];
    const float* db2 = (const float*)d_in[base + 9];
    const float* D3  = (const float*)d_in[base + 10];
    const float* db3 = (const float*)d_in[base + 11];
    float* out = (float*)d_out;

    float *bufA, *bufB, *sums;
    cudaGetSymbolAddress((void**)&bufA, g_bufA);
    cudaGetSymbolAddress((void**)&bufB, g_bufB);
    cudaGetSymbolAddress((void**)&sums, g_sums);

    const dim3 blk(NTHREADS);
    const dim3 grd(HF / BN, NN / BM);  // (4, 64)

    // layer 1
    gemm_tf32<false, false><<<grd, blk>>>(X,    W1,   bufA, nullptr, NN, HF, 256);
    gemm_tf32<true,  true ><<<grd, blk>>>(adj,  bufA, bufB, b1,      NN, HF, NN);
    // layer 2
    gemm_tf32<false, false><<<grd, blk>>>(bufB, W2,   bufA, nullptr, NN, HF, HF);
    gemm_tf32<true,  true ><<<grd, blk>>>(adj,  bufA, bufB, b2,      NN, HF, NN);
    // layer 3 (no relu)
    gemm_tf32<false, false><<<grd, blk>>>(bufB, W3,   bufA, nullptr, NN, HF, HF);
    gemm_tf32<false, true ><<<grd, blk>>>(adj,  bufA, bufB, b3,      NN, HF, NN);

    // readout + tail
    zero_sums<<<(GRAPHS * HF) / 256, 256>>>(sums);
    readout<<<dim3(HF / 64, NN / 512), 64>>>(bufB, seg, sums);
    mlp_tail<<<1, 1024>>>(sums, seg, D1, db1, D2, db2, D3, db3, out);
}

// round 4
// speedup vs baseline: 1.1370x; 1.1370x over previous
#include <cuda_runtime.h>
#include <cstdint>
#include <math.h>

// ---------------------------------------------------------------------------
// GCNGraph on sm_100 (no tcgen05 in this toolchain -> legacy mma.sync tf32).
//   L1: h = relu(adj @ (X@W1) + b1)
//   L2: h = relu(adj @ (h@W2) + b2)
//   L3 (no relu, folded into readout):
//       mean_s(adj @ hW3 + b3) = R[s,:] @ (h@W3) / cnt_s + b3,
//       with R = segment rowsum of adj  (removes one 8192^2x512 GEMM!)
//   then MLP tail + sigmoid.
// Big GEMMs: tf32 mma.sync, cp.async 4-stage pipeline, conflict-free smem.
// ---------------------------------------------------------------------------

#define NN      8192
#define HF      512
#define GRAPHS  64

// scratch (no allocations allowed)
__device__ float g_adjC[(size_t)NN * NN];   // rna-rounded adjacency
__device__ float g_bufA[NN * HF];           // h@W (tf32-rounded for big GEMM)
__device__ float g_bufB[NN * HF];           // layer output h
__device__ float g_R[GRAPHS * NN];          // segment rowsums of adj
__device__ float g_G[GRAPHS * HF];          // segment sums of layer-3 output

__device__ __forceinline__ uint32_t f2tf32(float x) {
    uint32_t r;
    asm("cvt.rna.tf32.f32 %0, %1;" : "=r"(r) : "f"(x));
    return r;
}
__device__ __forceinline__ uint32_t smem_u32(const void* p) {
    uint32_t a;
    asm("{ .reg .u64 t; cvta.to.shared.u64 t, %1; cvt.u32.u64 %0, t; }" : "=r"(a) : "l"(p));
    return a;
}
__device__ __forceinline__ void mma_frag(float* c, const uint32_t* a, const uint32_t* b) {
    asm volatile(
        "mma.sync.aligned.m16n8k8.row.col.f32.tf32.tf32.f32 "
        "{%0,%1,%2,%3}, {%4,%5,%6,%7}, {%8,%9}, {%0,%1,%2,%3};"
        : "+f"(c[0]), "+f"(c[1]), "+f"(c[2]), "+f"(c[3])
        : "r"(a[0]), "r"(a[1]), "r"(a[2]), "r"(a[3]), "r"(b[0]), "r"(b[1]));
}

// ========================= big GEMM (adj @ hW) ==============================
// C[8192,512] = A[8192,8192] @ B[8192,512], operands pre-rounded to tf32.

#define STG 4
#define GBM 128
#define GBN 128
#define GBK 16
#define AS_STRIDE 20     // 16 + 4 pad  (bank-conflict-free frag loads)
#define BS_STRIDE 136    // 128 + 8 pad
#define AS_FLOATS (GBM * AS_STRIDE)               // 2560
#define BS_FLOATS (GBK * BS_STRIDE)               // 2176
#define STAGE_FLOATS (AS_FLOATS + BS_FLOATS)      // 4736
#define BIG_SMEM (STG * STAGE_FLOATS * 4)         // 75776 bytes

__global__ void __launch_bounds__(256, 2)
big_gemm(const float* __restrict__ A, const float* __restrict__ B,
         float* __restrict__ C, const float* __restrict__ bias, int relu)
{
    extern __shared__ float smem[];

    const int tid  = threadIdx.x;
    const int warp = tid >> 5;
    const int lane = tid & 31;
    const int bm = blockIdx.y * GBM;
    const int bn = blockIdx.x * GBN;
    const int wm = (warp >> 2) * 64;
    const int wn = (warp & 3) * 32;
    const int g  = lane >> 2;
    const int q  = lane & 3;
    const int nk = NN / GBK;   // 512

    float acc[4][4][4];
    #pragma unroll
    for (int i = 0; i < 4; i++)
        #pragma unroll
        for (int j = 0; j < 4; j++)
            #pragma unroll
            for (int r = 0; r < 4; r++) acc[i][j][r] = 0.f;

    // per-thread copy chunks (16B each): 2 for A, 2 for B
    const int ar0 = tid >> 2,  ac0 = (tid & 3) * 4;         // chunks tid, tid+256
    const int br0 = tid >> 5,  bc0 = (tid & 31) * 4;

    auto issue = [&](int slot, int k0) {
        float* As = smem + slot * STAGE_FLOATS;
        float* Bs = As + AS_FLOATS;
        const uint32_t ab = smem_u32(As);
        const uint32_t bb = smem_u32(Bs);
        #pragma unroll
        for (int p = 0; p < 2; p++) {
            const int ar = ar0 + p * 64;
            asm volatile("cp.async.cg.shared.global [%0], [%1], 16;" ::
                "r"(ab + (uint32_t)(ar * AS_STRIDE + ac0) * 4u),
                "l"(A + (size_t)(bm + ar) * NN + k0 + ac0));
            const int br = br0 + p * 8;
            asm volatile("cp.async.cg.shared.global [%0], [%1], 16;" ::
                "r"(bb + (uint32_t)(br * BS_STRIDE + bc0) * 4u),
                "l"(B + (size_t)(k0 + br) * HF + bn + bc0));
        }
        asm volatile("cp.async.commit_group;" ::: "memory");
    };

    // prologue: 3 stages in flight
    issue(0, 0);
    issue(1, GBK);
    issue(2, 2 * GBK);

    for (int t = 0; t < nk; t++) {
        asm volatile("cp.async.wait_group 2;" ::: "memory");
        __syncthreads();
        if (t + 3 < nk) issue((t + 3) & 3, (t + 3) * GBK);

        const float* As = smem + (t & 3) * STAGE_FLOATS;
        const float* Bs = As + AS_FLOATS;
        #pragma unroll
        for (int kk = 0; kk < GBK; kk += 8) {
            uint32_t af[4][4], bf[4][2];
            #pragma unroll
            for (int i = 0; i < 4; i++) {
                const int r0 = wm + i * 16 + g;
                af[i][0] = __float_as_uint(As[r0 * AS_STRIDE + kk + q]);
                af[i][1] = __float_as_uint(As[(r0 + 8) * AS_STRIDE + kk + q]);
                af[i][2] = __float_as_uint(As[r0 * AS_STRIDE + kk + q + 4]);
                af[i][3] = __float_as_uint(As[(r0 + 8) * AS_STRIDE + kk + q + 4]);
            }
            #pragma unroll
            for (int j = 0; j < 4; j++) {
                const int c0 = wn + j * 8 + g;
                bf[j][0] = __float_as_uint(Bs[(kk + q) * BS_STRIDE + c0]);
                bf[j][1] = __float_as_uint(Bs[(kk + q + 4) * BS_STRIDE + c0]);
            }
            #pragma unroll
            for (int i = 0; i < 4; i++)
                #pragma unroll
                for (int j = 0; j < 4; j++)
                    mma_frag(acc[i][j], af[i], bf[j]);
        }
    }

    // epilogue: bias + relu, tf32-round (output feeds next tf32 GEMM's A/B)
    #pragma unroll
    for (int i = 0; i < 4; i++) {
        #pragma unroll
        for (int j = 0; j < 4; j++) {
            const int row = bm + wm + i * 16 + g;
            const int col = bn + wn + j * 8 + 2 * q;
            const float bv0 = bias[col], bv1 = bias[col + 1];
            float v0 = acc[i][j][0] + bv0;
            float v1 = acc[i][j][1] + bv1;
            float v2 = acc[i][j][2] + bv0;
            float v3 = acc[i][j][3] + bv1;
            if (relu) {
                v0 = fmaxf(v0, 0.f); v1 = fmaxf(v1, 0.f);
                v2 = fmaxf(v2, 0.f); v3 = fmaxf(v3, 0.f);
            }
            *(float2*)(C + (size_t)row * HF + col)       = make_float2(v0, v1);
            *(float2*)(C + (size_t)(row + 8) * HF + col) = make_float2(v2, v3);
        }
    }
}

// ================== small SIMT tf32 GEMM (H @ W) ===========================
// C[M,N] = A[M,K] @ B[K,N], normal row-major store, optional tf32 rounding.

#define BM 128
#define BN 128
#define BK 16
#define NTHREADS 256

template <bool ROUND>
__global__ void __launch_bounds__(NTHREADS)
gemm_small(const float* __restrict__ A, const float* __restrict__ B,
           float* __restrict__ C, int M, int N, int K)
{
    __shared__ uint32_t As[2][BM][BK + 4];
    __shared__ uint32_t Bs[2][BK][BN + 8];

    const int bm = blockIdx.y * BM;
    const int bn = blockIdx.x * BN;
    const int tid  = threadIdx.x;
    const int warp = tid >> 5;
    const int lane = tid & 31;
    const int wm = (warp >> 2) * 64;
    const int wn = (warp & 3) * 32;
    const int g  = lane >> 2;
    const int q  = lane & 3;

    float acc[4][4][4];
    #pragma unroll
    for (int i = 0; i < 4; i++)
        #pragma unroll
        for (int j = 0; j < 4; j++)
            #pragma unroll
            for (int r = 0; r < 4; r++) acc[i][j][r] = 0.f;

    const int arow = tid >> 2;
    const int acol = (tid & 3) * 4;
    const int brow = tid >> 5;
    const int bcol = (tid & 31) * 4;
    const int nk = K / BK;

    float4 ra0, ra1, rb0, rb1;
    ra0 = *(const float4*)(A + (size_t)(bm + arow) * K + acol);
    ra1 = *(const float4*)(A + (size_t)(bm + arow + 64) * K + acol);
    rb0 = *(const float4*)(B + (size_t)(brow) * N + bn + bcol);
    rb1 = *(const float4*)(B + (size_t)(brow + 8) * N + bn + bcol);
    {
        uint4 u;
        u.x = f2tf32(ra0.x); u.y = f2tf32(ra0.y); u.z = f2tf32(ra0.z); u.w = f2tf32(ra0.w);
        *(uint4*)&As[0][arow][acol] = u;
        u.x = f2tf32(ra1.x); u.y = f2tf32(ra1.y); u.z = f2tf32(ra1.z); u.w = f2tf32(ra1.w);
        *(uint4*)&As[0][arow + 64][acol] = u;
        u.x = f2tf32(rb0.x); u.y = f2tf32(rb0.y); u.z = f2tf32(rb0.z); u.w = f2tf32(rb0.w);
        *(uint4*)&Bs[0][brow][bcol] = u;
        u.x = f2tf32(rb1.x); u.y = f2tf32(rb1.y); u.z = f2tf32(rb1.z); u.w = f2tf32(rb1.w);
        *(uint4*)&Bs[0][brow + 8][bcol] = u;
    }
    __syncthreads();

    for (int t = 0; t < nk; t++) {
        const int cur = t & 1;
        const int nxt = cur ^ 1;
        const bool more = (t + 1 < nk);
        if (more) {
            const int k0 = (t + 1) * BK;
            ra0 = *(const float4*)(A + (size_t)(bm + arow) * K + k0 + acol);
            ra1 = *(const float4*)(A + (size_t)(bm + arow + 64) * K + k0 + acol);
            rb0 = *(const float4*)(B + (size_t)(k0 + brow) * N + bn + bcol);
            rb1 = *(const float4*)(B + (size_t)(k0 + brow + 8) * N + bn + bcol);
        }
        #pragma unroll
        for (int kk = 0; kk < BK; kk += 8) {
            uint32_t af[4][4], bf[4][2];
            #pragma unroll
            for (int i = 0; i < 4; i++) {
                const int r0 = wm + i * 16 + g;
                af[i][0] = As[cur][r0][kk + q];
                af[i][1] = As[cur][r0 + 8][kk + q];
                af[i][2] = As[cur][r0][kk + q + 4];
                af[i][3] = As[cur][r0 + 8][kk + q + 4];
            }
            #pragma unroll
            for (int j = 0; j < 4; j++) {
                const int c0 = wn + j * 8 + g;
                bf[j][0] = Bs[cur][kk + q][c0];
                bf[j][1] = Bs[cur][kk + q + 4][c0];
            }
            #pragma unroll
            for (int i = 0; i < 4; i++)
                #pragma unroll
                for (int j = 0; j < 4; j++)
                    mma_frag(acc[i][j], af[i], bf[j]);
        }
        if (more) {
            uint4 u;
            u.x = f2tf32(ra0.x); u.y = f2tf32(ra0.y); u.z = f2tf32(ra0.z); u.w = f2tf32(ra0.w);
            *(uint4*)&As[nxt][arow][acol] = u;
            u.x = f2tf32(ra1.x); u.y = f2tf32(ra1.y); u.z = f2tf32(ra1.z); u.w = f2tf32(ra1.w);
            *(uint4*)&As[nxt][arow + 64][acol] = u;
            u.x = f2tf32(rb0.x); u.y = f2tf32(rb0.y); u.z = f2tf32(rb0.z); u.w = f2tf32(rb0.w);
            *(uint4*)&Bs[nxt][brow][bcol] = u;
            u.x = f2tf32(rb1.x); u.y = f2tf32(rb1.y); u.z = f2tf32(rb1.z); u.w = f2tf32(rb1.w);
            *(uint4*)&Bs[nxt][brow + 8][bcol] = u;
        }
        __syncthreads();
    }

    #pragma unroll
    for (int i = 0; i < 4; i++) {
        #pragma unroll
        for (int j = 0; j < 4; j++) {
            const int row = bm + wm + i * 16 + g;
            const int col = bn + wn + j * 8 + 2 * q;
            float v0 = acc[i][j][0], v1 = acc[i][j][1];
            float v2 = acc[i][j][2], v3 = acc[i][j][3];
            if (ROUND) {
                v0 = __uint_as_float(f2tf32(v0)); v1 = __uint_as_float(f2tf32(v1));
                v2 = __uint_as_float(f2tf32(v2)); v3 = __uint_as_float(f2tf32(v3));
            }
            *(float2*)(C + (size_t)row * N + col)       = make_float2(v0, v1);
            *(float2*)(C + (size_t)(row + 8) * N + col) = make_float2(v2, v3);
        }
    }
}

// =============================== helpers ====================================

__global__ void conv_rna(const float4* __restrict__ in, float4* __restrict__ out, int n4) {
    for (int i = blockIdx.x * blockDim.x + threadIdx.x; i < n4; i += gridDim.x * blockDim.x) {
        float4 v = in[i];
        float4 o;
        o.x = __uint_as_float(f2tf32(v.x));
        o.y = __uint_as_float(f2tf32(v.y));
        o.z = __uint_as_float(f2tf32(v.z));
        o.w = __uint_as_float(f2tf32(v.w));
        out[i] = o;
    }
}

__global__ void zero_buf(float* __restrict__ p, int n) {
    const int i = blockIdx.x * blockDim.x + threadIdx.x;
    if (i < n) p[i] = 0.f;
}

// R[s][col] = sum of adj rows in segment s (seg sorted -> run-length direct store)
__global__ void segrow(const float* __restrict__ adj, const int* __restrict__ seg,
                       float* __restrict__ R)
{
    __shared__ int sseg[NN];
    const int col = blockIdx.x * 256 + threadIdx.x;
    for (int i = threadIdx.x; i < NN; i += 256) sseg[i] = seg[i];
    __syncthreads();

    float acc = 0.f;
    int cur = sseg[0];
    for (int i = 0; i < NN; i++) {
        const int s = sseg[i];
        if (s != cur) {
            R[(size_t)cur * NN + col] = acc;
            acc = 0.f;
            cur = s;
        }
        acc += adj[(size_t)i * NN + col];
    }
    R[(size_t)cur * NN + col] = acc;
}

// G[64,512] += R[64,8192] @ H[8192,512]  (fp32 SIMT, k-split with atomics)
__global__ void __launch_bounds__(256)
tiny_gemm(const float* __restrict__ R, const float* __restrict__ H,
          float* __restrict__ G)
{
    __shared__ float sA[64][33];
    __shared__ float sB[32][132];
    const int tid = threadIdx.x;
    const int bn = blockIdx.x * 128;
    const int k0 = blockIdx.y * 512;
    const int row0 = (tid >> 5) * 8;
    const int col0 = (tid & 31) * 4;

    float acc[8][4];
    #pragma unroll
    for (int r = 0; r < 8; r++)
        #pragma unroll
        for (int c = 0; c < 4; c++) acc[r][c] = 0.f;

    for (int kt = 0; kt < 512; kt += 32) {
        const int k = k0 + kt;
        #pragma unroll
        for (int i = 0; i < 8; i++) {
            const int e = tid + 256 * i;
            sA[e >> 5][e & 31] = R[(size_t)(e >> 5) * NN + k + (e & 31)];
        }
        #pragma unroll
        for (int i = 0; i < 16; i++) {
            const int e = tid + 256 * i;
            sB[e >> 7][e & 127] = H[(size_t)(k + (e >> 7)) * HF + bn + (e & 127)];
        }
        __syncthreads();
        #pragma unroll
        for (int kk = 0; kk < 32; kk++) {
            const float4 b4 = *(const float4*)&sB[kk][col0];
            #pragma unroll
            for (int r = 0; r < 8; r++) {
                const float a = sA[row0 + r][kk];
                acc[r][0] += a * b4.x;
                acc[r][1] += a * b4.y;
                acc[r][2] += a * b4.z;
                acc[r][3] += a * b4.w;
            }
        }
        __syncthreads();
    }
    #pragma unroll
    for (int r = 0; r < 8; r++)
        #pragma unroll
        for (int c = 0; c < 4; c++)
            atomicAdd(&G[(row0 + r) * HF + bn + col0 + c], acc[r][c]);
}

// mean + b3 + MLP (512->16->8->1) + sigmoid. one block, 1024 threads.
__global__ void mlp_tail(const float* __restrict__ G, const int* __restrict__ seg,
                         const float* __restrict__ b3,
                         const float* __restrict__ D1, const float* __restrict__ db1,
                         const float* __restrict__ D2, const float* __restrict__ db2,
                         const float* __restrict__ D3, const float* __restrict__ db3,
                         float* __restrict__ out)
{
    __shared__ int   cnt[GRAPHS];
    __shared__ float s1[GRAPHS][16];
    __shared__ float s2[GRAPHS][8];
    const int tid = threadIdx.x;

    if (tid < GRAPHS) cnt[tid] = 0;
    __syncthreads();
    for (int n = tid; n < NN; n += 1024) atomicAdd(&cnt[seg[n]], 1);
    __syncthreads();

    {   // stage 1
        const int gph = tid >> 4, j = tid & 15;
        const float inv = 1.f / (float)max(cnt[gph], 1);
        float acc = 0.f;
        const float* grow = G + gph * HF;
        for (int k = 0; k < HF; k++)
            acc += (grow[k] * inv + b3[k]) * D1[k * 16 + j];
        s1[gph][j] = fmaxf(acc + db1[j], 0.f);
    }
    __syncthreads();
    if (tid < 512) {  // stage 2
        const int gph = tid >> 3, j = tid & 7;
        float acc = 0.f;
        for (int k = 0; k < 16; k++) acc += s1[gph][k] * D2[k * 8 + j];
        s2[gph][j] = fmaxf(acc + db2[j], 0.f);
    }
    __syncthreads();
    if (tid < GRAPHS) {  // stage 3 + sigmoid
        float acc = 0.f;
        for (int k = 0; k < 8; k++) acc += s2[tid][k] * D3[k];
        out[tid] = 1.f / (1.f + expf(-(acc + db3[0])));
    }
}

// ================================= host =====================================

extern "C" void kernel_launch(void* const* d_in, const int* in_sizes, int n_in,
                              void* d_out, int out_size)
{
    const float* X   = (const float*)d_in[0];
    const float* adj = (const float*)d_in[1];
    const int*   seg = (const int*)d_in[2];
    const int base = n_in - 12;
    const float* W1  = (const float*)d_in[base + 0];
    const float* b1  = (const float*)d_in[base + 1];
    const float* W2  = (const float*)d_in[base + 2];
    const float* b2  = (const float*)d_in[base + 3];
    const float* W3  = (const float*)d_in[base + 4];
    const float* b3  = (const float*)d_in[base + 5];
    const float* D1  = (const float*)d_in[base + 6];
    const float* db1 = (const float*)d_in[base + 7];
    const float* D2  = (const float*)d_in[base + 8];
    const float* db2 = (const float*)d_in[base + 9];
    const float* D3  = (const float*)d_in[base + 10];
    const float* db3 = (const float*)d_in[base + 11];
    float* out = (float*)d_out;

    float *adjC, *bufA, *bufB, *R, *G;
    cudaGetSymbolAddress((void**)&adjC, g_adjC);
    cudaGetSymbolAddress((void**)&bufA, g_bufA);
    cudaGetSymbolAddress((void**)&bufB, g_bufB);
    cudaGetSymbolAddress((void**)&R, g_R);
    cudaGetSymbolAddress((void**)&G, g_G);

    static bool attr_set = false;
    if (!attr_set) {
        cudaFuncSetAttribute(big_gemm, cudaFuncAttributeMaxDynamicSharedMemorySize, BIG_SMEM);
        attr_set = true;
    }

    const dim3 blk(NTHREADS);
    const dim3 ggrd(HF / BN, NN / BM);   // (4, 64)

    // prep: rounded adjacency + segment rowsums + zeroed accumulators
    conv_rna<<<2048, 256>>>((const float4*)adj, (float4*)adjC, (NN * NN) / 4);
    zero_buf<<<(GRAPHS * NN + 255) / 256, 256>>>(R, GRAPHS * NN);
    zero_buf<<<(GRAPHS * HF + 255) / 256, 256>>>(G, GRAPHS * HF);
    segrow<<<NN / 256, 256>>>(adj, seg, R);

    // layer 1
    gemm_small<true><<<ggrd, blk>>>(X, W1, bufA, NN, HF, 256);
    big_gemm<<<ggrd, blk, BIG_SMEM>>>(adjC, bufA, bufB, b1, 1);
    // layer 2
    gemm_small<true><<<ggrd, blk>>>(bufB, W2, bufA, NN, HF, HF);
    big_gemm<<<ggrd, blk, BIG_SMEM>>>(adjC, bufA, bufB, b2, 1);
    // layer 3 folded: hW3 (fp32), then R @ hW3
    gemm_small<false><<<ggrd, blk>>>(bufB, W3, bufA, NN, HF, HF);
    tiny_gemm<<<dim3(HF / 128, NN / 512), 256>>>(R, bufA, G);

    // tail
    mlp_tail<<<1, 1024>>>(G, seg, b3, D1, db1, D2, db2, D3, db3, out);
}

// round 7
// speedup vs baseline: 1.6502x; 1.4513x over previous
#include <cuda_runtime.h>
#include <cstdint>
#include <math.h>

// ---------------------------------------------------------------------------
// GCNGraph on sm_100 (no tcgen05 in this toolchain -> legacy mma.sync tf32).
//   L1: h = relu(adj @ (X@W1) + b1)
//   L2: h = relu(adj @ (h@W2) + b2)
//   L3 (no relu, folded into readout):
//       mean_s(adj @ hW3 + b3) = R[s,:] @ (h@W3) / cnt_s + b3,
//       with R = segment rowsum of adj  (removes one 8192^2x512 GEMM!)
//   then MLP tail + sigmoid.
// Big GEMMs: tf32 mma.sync, cp.async 4-stage pipeline, conflict-free smem.
// R5: segrow fused with rna-conversion, fully parallel (was 672us @ 5% HBM).
// ---------------------------------------------------------------------------

#define NN      8192
#define HF      512
#define GRAPHS  64

// scratch (no allocations allowed)
__device__ float g_adjC[(size_t)NN * NN];   // rna-rounded adjacency
__device__ float g_bufA[NN * HF];           // h@W (tf32-rounded for big GEMM)
__device__ float g_bufB[NN * HF];           // layer output h
__device__ float g_R[GRAPHS * NN];          // segment rowsums of adj
__device__ float g_G[GRAPHS * HF];          // segment sums of layer-3 output

__device__ __forceinline__ uint32_t f2tf32(float x) {
    uint32_t r;
    asm("cvt.rna.tf32.f32 %0, %1;" : "=r"(r) : "f"(x));
    return r;
}
__device__ __forceinline__ uint32_t smem_u32(const void* p) {
    uint32_t a;
    asm("{ .reg .u64 t; cvta.to.shared.u64 t, %1; cvt.u32.u64 %0, t; }" : "=r"(a) : "l"(p));
    return a;
}
__device__ __forceinline__ void mma_frag(float* c, const uint32_t* a, const uint32_t* b) {
    asm volatile(
        "mma.sync.aligned.m16n8k8.row.col.f32.tf32.tf32.f32 "
        "{%0,%1,%2,%3}, {%4,%5,%6,%7}, {%8,%9}, {%0,%1,%2,%3};"
        : "+f"(c[0]), "+f"(c[1]), "+f"(c[2]), "+f"(c[3])
        : "r"(a[0]), "r"(a[1]), "r"(a[2]), "r"(a[3]), "r"(b[0]), "r"(b[1]));
}

// ========================= big GEMM (adj @ hW) ==============================
// C[8192,512] = A[8192,8192] @ B[8192,512], operands pre-rounded to tf32.

#define STG 4
#define GBM 128
#define GBN 128
#define GBK 16
#define AS_STRIDE 20     // 16 + 4 pad  (bank-conflict-free frag loads)
#define BS_STRIDE 136    // 128 + 8 pad
#define AS_FLOATS (GBM * AS_STRIDE)               // 2560
#define BS_FLOATS (GBK * BS_STRIDE)               // 2176
#define STAGE_FLOATS (AS_FLOATS + BS_FLOATS)      // 4736
#define BIG_SMEM (STG * STAGE_FLOATS * 4)         // 75776 bytes

__global__ void __launch_bounds__(256, 2)
big_gemm(const float* __restrict__ A, const float* __restrict__ B,
         float* __restrict__ C, const float* __restrict__ bias, int relu)
{
    extern __shared__ float smem[];

    const int tid  = threadIdx.x;
    const int warp = tid >> 5;
    const int lane = tid & 31;
    const int bm = blockIdx.y * GBM;
    const int bn = blockIdx.x * GBN;
    const int wm = (warp >> 2) * 64;
    const int wn = (warp & 3) * 32;
    const int g  = lane >> 2;
    const int q  = lane & 3;
    const int nk = NN / GBK;   // 512

    float acc[4][4][4];
    #pragma unroll
    for (int i = 0; i < 4; i++)
        #pragma unroll
        for (int j = 0; j < 4; j++)
            #pragma unroll
            for (int r = 0; r < 4; r++) acc[i][j][r] = 0.f;

    // per-thread copy chunks (16B each): 2 for A, 2 for B
    const int ar0 = tid >> 2,  ac0 = (tid & 3) * 4;         // chunks tid, tid+256
    const int br0 = tid >> 5,  bc0 = (tid & 31) * 4;

    auto issue = [&](int slot, int k0) {
        float* As = smem + slot * STAGE_FLOATS;
        float* Bs = As + AS_FLOATS;
        const uint32_t ab = smem_u32(As);
        const uint32_t bb = smem_u32(Bs);
        #pragma unroll
        for (int p = 0; p < 2; p++) {
            const int ar = ar0 + p * 64;
            asm volatile("cp.async.cg.shared.global [%0], [%1], 16;" ::
                "r"(ab + (uint32_t)(ar * AS_STRIDE + ac0) * 4u),
                "l"(A + (size_t)(bm + ar) * NN + k0 + ac0));
            const int br = br0 + p * 8;
            asm volatile("cp.async.cg.shared.global [%0], [%1], 16;" ::
                "r"(bb + (uint32_t)(br * BS_STRIDE + bc0) * 4u),
                "l"(B + (size_t)(k0 + br) * HF + bn + bc0));
        }
        asm volatile("cp.async.commit_group;" ::: "memory");
    };

    // prologue: 3 stages in flight
    issue(0, 0);
    issue(1, GBK);
    issue(2, 2 * GBK);

    for (int t = 0; t < nk; t++) {
        asm volatile("cp.async.wait_group 2;" ::: "memory");
        __syncthreads();
        if (t + 3 < nk) issue((t + 3) & 3, (t + 3) * GBK);

        const float* As = smem + (t & 3) * STAGE_FLOATS;
        const float* Bs = As + AS_FLOATS;
        #pragma unroll
        for (int kk = 0; kk < GBK; kk += 8) {
            uint32_t af[4][4], bf[4][2];
            #pragma unroll
            for (int i = 0; i < 4; i++) {
                const int r0 = wm + i * 16 + g;
                af[i][0] = __float_as_uint(As[r0 * AS_STRIDE + kk + q]);
                af[i][1] = __float_as_uint(As[(r0 + 8) * AS_STRIDE + kk + q]);
                af[i][2] = __float_as_uint(As[r0 * AS_STRIDE + kk + q + 4]);
                af[i][3] = __float_as_uint(As[(r0 + 8) * AS_STRIDE + kk + q + 4]);
            }
            #pragma unroll
            for (int j = 0; j < 4; j++) {
                const int c0 = wn + j * 8 + g;
                bf[j][0] = __float_as_uint(Bs[(kk + q) * BS_STRIDE + c0]);
                bf[j][1] = __float_as_uint(Bs[(kk + q + 4) * BS_STRIDE + c0]);
            }
            #pragma unroll
            for (int i = 0; i < 4; i++)
                #pragma unroll
                for (int j = 0; j < 4; j++)
                    mma_frag(acc[i][j], af[i], bf[j]);
        }
    }

    // epilogue: bias + relu, tf32-round (output feeds next tf32 GEMM's A/B)
    #pragma unroll
    for (int i = 0; i < 4; i++) {
        #pragma unroll
        for (int j = 0; j < 4; j++) {
            const int row = bm + wm + i * 16 + g;
            const int col = bn + wn + j * 8 + 2 * q;
            const float bv0 = bias[col], bv1 = bias[col + 1];
            float v0 = acc[i][j][0] + bv0;
            float v1 = acc[i][j][1] + bv1;
            float v2 = acc[i][j][2] + bv0;
            float v3 = acc[i][j][3] + bv1;
            if (relu) {
                v0 = fmaxf(v0, 0.f); v1 = fmaxf(v1, 0.f);
                v2 = fmaxf(v2, 0.f); v3 = fmaxf(v3, 0.f);
            }
            *(float2*)(C + (size_t)row * HF + col)       = make_float2(v0, v1);
            *(float2*)(C + (size_t)(row + 8) * HF + col) = make_float2(v2, v3);
        }
    }
}

// ================== small SIMT tf32 GEMM (H @ W) ===========================
// C[M,N] = A[M,K] @ B[K,N], normal row-major store, optional tf32 rounding.

#define BM 128
#define BN 128
#define BK 16
#define NTHREADS 256

template <bool ROUND>
__global__ void __launch_bounds__(NTHREADS)
gemm_small(const float* __restrict__ A, const float* __restrict__ B,
           float* __restrict__ C, int M, int N, int K)
{
    __shared__ uint32_t As[2][BM][BK + 4];
    __shared__ uint32_t Bs[2][BK][BN + 8];

    const int bm = blockIdx.y * BM;
    const int bn = blockIdx.x * BN;
    const int tid  = threadIdx.x;
    const int warp = tid >> 5;
    const int lane = tid & 31;
    const int wm = (warp >> 2) * 64;
    const int wn = (warp & 3) * 32;
    const int g  = lane >> 2;
    const int q  = lane & 3;

    float acc[4][4][4];
    #pragma unroll
    for (int i = 0; i < 4; i++)
        #pragma unroll
        for (int j = 0; j < 4; j++)
            #pragma unroll
            for (int r = 0; r < 4; r++) acc[i][j][r] = 0.f;

    const int arow = tid >> 2;
    const int acol = (tid & 3) * 4;
    const int brow = tid >> 5;
    const int bcol = (tid & 31) * 4;
    const int nk = K / BK;

    float4 ra0, ra1, rb0, rb1;
    ra0 = *(const float4*)(A + (size_t)(bm + arow) * K + acol);
    ra1 = *(const float4*)(A + (size_t)(bm + arow + 64) * K + acol);
    rb0 = *(const float4*)(B + (size_t)(brow) * N + bn + bcol);
    rb1 = *(const float4*)(B + (size_t)(brow + 8) * N + bn + bcol);
    {
        uint4 u;
        u.x = f2tf32(ra0.x); u.y = f2tf32(ra0.y); u.z = f2tf32(ra0.z); u.w = f2tf32(ra0.w);
        *(uint4*)&As[0][arow][acol] = u;
        u.x = f2tf32(ra1.x); u.y = f2tf32(ra1.y); u.z = f2tf32(ra1.z); u.w = f2tf32(ra1.w);
        *(uint4*)&As[0][arow + 64][acol] = u;
        u.x = f2tf32(rb0.x); u.y = f2tf32(rb0.y); u.z = f2tf32(rb0.z); u.w = f2tf32(rb0.w);
        *(uint4*)&Bs[0][brow][bcol] = u;
        u.x = f2tf32(rb1.x); u.y = f2tf32(rb1.y); u.z = f2tf32(rb1.z); u.w = f2tf32(rb1.w);
        *(uint4*)&Bs[0][brow + 8][bcol] = u;
    }
    __syncthreads();

    for (int t = 0; t < nk; t++) {
        const int cur = t & 1;
        const int nxt = cur ^ 1;
        const bool more = (t + 1 < nk);
        if (more) {
            const int k0 = (t + 1) * BK;
            ra0 = *(const float4*)(A + (size_t)(bm + arow) * K + k0 + acol);
            ra1 = *(const float4*)(A + (size_t)(bm + arow + 64) * K + k0 + acol);
            rb0 = *(const float4*)(B + (size_t)(k0 + brow) * N + bn + bcol);
            rb1 = *(const float4*)(B + (size_t)(k0 + brow + 8) * N + bn + bcol);
        }
        #pragma unroll
        for (int kk = 0; kk < BK; kk += 8) {
            uint32_t af[4][4], bf[4][2];
            #pragma unroll
            for (int i = 0; i < 4; i++) {
                const int r0 = wm + i * 16 + g;
                af[i][0] = As[cur][r0][kk + q];
                af[i][1] = As[cur][r0 + 8][kk + q];
                af[i][2] = As[cur][r0][kk + q + 4];
                af[i][3] = As[cur][r0 + 8][kk + q + 4];
            }
            #pragma unroll
            for (int j = 0; j < 4; j++) {
                const int c0 = wn + j * 8 + g;
                bf[j][0] = Bs[cur][kk + q][c0];
                bf[j][1] = Bs[cur][kk + q + 4][c0];
            }
            #pragma unroll
            for (int i = 0; i < 4; i++)
                #pragma unroll
                for (int j = 0; j < 4; j++)
                    mma_frag(acc[i][j], af[i], bf[j]);
        }
        if (more) {
            uint4 u;
            u.x = f2tf32(ra0.x); u.y = f2tf32(ra0.y); u.z = f2tf32(ra0.z); u.w = f2tf32(ra0.w);
            *(uint4*)&As[nxt][arow][acol] = u;
            u.x = f2tf32(ra1.x); u.y = f2tf32(ra1.y); u.z = f2tf32(ra1.z); u.w = f2tf32(ra1.w);
            *(uint4*)&As[nxt][arow + 64][acol] = u;
            u.x = f2tf32(rb0.x); u.y = f2tf32(rb0.y); u.z = f2tf32(rb0.z); u.w = f2tf32(rb0.w);
            *(uint4*)&Bs[nxt][brow][bcol] = u;
            u.x = f2tf32(rb1.x); u.y = f2tf32(rb1.y); u.z = f2tf32(rb1.z); u.w = f2tf32(rb1.w);
            *(uint4*)&Bs[nxt][brow + 8][bcol] = u;
        }
        __syncthreads();
    }

    #pragma unroll
    for (int i = 0; i < 4; i++) {
        #pragma unroll
        for (int j = 0; j < 4; j++) {
            const int row = bm + wm + i * 16 + g;
            const int col = bn + wn + j * 8 + 2 * q;
            float v0 = acc[i][j][0], v1 = acc[i][j][1];
            float v2 = acc[i][j][2], v3 = acc[i][j][3];
            if (ROUND) {
                v0 = __uint_as_float(f2tf32(v0)); v1 = __uint_as_float(f2tf32(v1));
                v2 = __uint_as_float(f2tf32(v2)); v3 = __uint_as_float(f2tf32(v3));
            }
            *(float2*)(C + (size_t)row * N + col)       = make_float2(v0, v1);
            *(float2*)(C + (size_t)(row + 8) * N + col) = make_float2(v2, v3);
        }
    }
}

// =============================== helpers ====================================

// Fused: adjC = rna(adj)  AND  R[s][col] += column-wise segment rowsums.
// Grid (NN/1024 cols, NN/CHUNK rows) = (8, 32), 256 threads, float4 per thread.
#define SR_CHUNK 256

__global__ void __launch_bounds__(256)
segrow_conv(const float* __restrict__ adj, const int* __restrict__ seg,
            float* __restrict__ adjC, float* __restrict__ R)
{
    const int col = (blockIdx.x * 256 + threadIdx.x) * 4;
    const int r0  = blockIdx.y * SR_CHUNK;
    const int r1  = r0 + SR_CHUNK;

    float4 acc = make_float4(0.f, 0.f, 0.f, 0.f);
    int cur = seg[r0];

    #pragma unroll 4
    for (int i = r0; i < r1; i++) {
        const int s = __ldg(&seg[i]);
        if (s != cur) {
            atomicAdd(&R[(size_t)cur * NN + col],     acc.x);
            atomicAdd(&R[(size_t)cur * NN + col + 1], acc.y);
            atomicAdd(&R[(size_t)cur * NN + col + 2], acc.z);
            atomicAdd(&R[(size_t)cur * NN + col + 3], acc.w);
            acc = make_float4(0.f, 0.f, 0.f, 0.f);
            cur = s;
        }
        const float4 v = *(const float4*)(adj + (size_t)i * NN + col);
        acc.x += v.x; acc.y += v.y; acc.z += v.z; acc.w += v.w;
        float4 o;
        o.x = __uint_as_float(f2tf32(v.x));
        o.y = __uint_as_float(f2tf32(v.y));
        o.z = __uint_as_float(f2tf32(v.z));
        o.w = __uint_as_float(f2tf32(v.w));
        *(float4*)(adjC + (size_t)i * NN + col) = o;
    }
    atomicAdd(&R[(size_t)cur * NN + col],     acc.x);
    atomicAdd(&R[(size_t)cur * NN + col + 1], acc.y);
    atomicAdd(&R[(size_t)cur * NN + col + 2], acc.z);
    atomicAdd(&R[(size_t)cur * NN + col + 3], acc.w);
}

__global__ void zero_buf(float* __restrict__ p, int n) {
    const int i = blockIdx.x * blockDim.x + threadIdx.x;
    if (i < n) p[i] = 0.f;
}

// G[64,512] += R[64,8192] @ H[8192,512]  (fp32 SIMT, k-split with atomics)
__global__ void __launch_bounds__(256)
tiny_gemm(const float* __restrict__ R, const float* __restrict__ H,
          float* __restrict__ G)
{
    __shared__ float sA[64][33];
    __shared__ float sB[32][132];
    const int tid = threadIdx.x;
    const int bn = blockIdx.x * 128;
    const int k0 = blockIdx.y * 512;
    const int row0 = (tid >> 5) * 8;
    const int col0 = (tid & 31) * 4;

    float acc[8][4];
    #pragma unroll
    for (int r = 0; r < 8; r++)
        #pragma unroll
        for (int c = 0; c < 4; c++) acc[r][c] = 0.f;

    for (int kt = 0; kt < 512; kt += 32) {
        const int k = k0 + kt;
        #pragma unroll
        for (int i = 0; i < 8; i++) {
            const int e = tid + 256 * i;
            sA[e >> 5][e & 31] = R[(size_t)(e >> 5) * NN + k + (e & 31)];
        }
        #pragma unroll
        for (int i = 0; i < 16; i++) {
            const int e = tid + 256 * i;
            sB[e >> 7][e & 127] = H[(size_t)(k + (e >> 7)) * HF + bn + (e & 127)];
        }
        __syncthreads();
        #pragma unroll
        for (int kk = 0; kk < 32; kk++) {
            const float4 b4 = *(const float4*)&sB[kk][col0];
            #pragma unroll
            for (int r = 0; r < 8; r++) {
                const float a = sA[row0 + r][kk];
                acc[r][0] += a * b4.x;
                acc[r][1] += a * b4.y;
                acc[r][2] += a * b4.z;
                acc[r][3] += a * b4.w;
            }
        }
        __syncthreads();
    }
    #pragma unroll
    for (int r = 0; r < 8; r++)
        #pragma unroll
        for (int c = 0; c < 4; c++)
            atomicAdd(&G[(row0 + r) * HF + bn + col0 + c], acc[r][c]);
}

// mean + b3 + MLP (512->16->8->1) + sigmoid. one block, 1024 threads.
__global__ void mlp_tail(const float* __restrict__ G, const int* __restrict__ seg,
                         const float* __restrict__ b3,
                         const float* __restrict__ D1, const float* __restrict__ db1,
                         const float* __restrict__ D2, const float* __restrict__ db2,
                         const float* __restrict__ D3, const float* __restrict__ db3,
                         float* __restrict__ out)
{
    __shared__ int   cnt[GRAPHS];
    __shared__ float s1[GRAPHS][16];
    __shared__ float s2[GRAPHS][8];
    const int tid = threadIdx.x;

    if (tid < GRAPHS) cnt[tid] = 0;
    __syncthreads();
    for (int n = tid; n < NN; n += 1024) atomicAdd(&cnt[seg[n]], 1);
    __syncthreads();

    {   // stage 1
        const int gph = tid >> 4, j = tid & 15;
        const float inv = 1.f / (float)max(cnt[gph], 1);
        float acc = 0.f;
        const float* grow = G + gph * HF;
        for (int k = 0; k < HF; k++)
            acc += (grow[k] * inv + b3[k]) * D1[k * 16 + j];
        s1[gph][j] = fmaxf(acc + db1[j], 0.f);
    }
    __syncthreads();
    if (tid < 512) {  // stage 2
        const int gph = tid >> 3, j = tid & 7;
        float acc = 0.f;
        for (int k = 0; k < 16; k++) acc += s1[gph][k] * D2[k * 8 + j];
        s2[gph][j] = fmaxf(acc + db2[j], 0.f);
    }
    __syncthreads();
    if (tid < GRAPHS) {  // stage 3 + sigmoid
        float acc = 0.f;
        for (int k = 0; k < 8; k++) acc += s2[tid][k] * D3[k];
        out[tid] = 1.f / (1.f + expf(-(acc + db3[0])));
    }
}

// ================================= host =====================================

extern "C" void kernel_launch(void* const* d_in, const int* in_sizes, int n_in,
                              void* d_out, int out_size)
{
    const float* X   = (const float*)d_in[0];
    const float* adj = (const float*)d_in[1];
    const int*   seg = (const int*)d_in[2];
    const int base = n_in - 12;
    const float* W1  = (const float*)d_in[base + 0];
    const float* b1  = (const float*)d_in[base + 1];
    const float* W2  = (const float*)d_in[base + 2];
    const float* b2  = (const float*)d_in[base + 3];
    const float* W3  = (const float*)d_in[base + 4];
    const float* b3  = (const float*)d_in[base + 5];
    const float* D1  = (const float*)d_in[base + 6];
    const float* db1 = (const float*)d_in[base + 7];
    const float* D2  = (const float*)d_in[base + 8];
    const float* db2 = (const float*)d_in[base + 9];
    const float* D3  = (const float*)d_in[base + 10];
    const float* db3 = (const float*)d_in[base + 11];
    float* out = (float*)d_out;

    float *adjC, *bufA, *bufB, *R, *G;
    cudaGetSymbolAddress((void**)&adjC, g_adjC);
    cudaGetSymbolAddress((void**)&bufA, g_bufA);
    cudaGetSymbolAddress((void**)&bufB, g_bufB);
    cudaGetSymbolAddress((void**)&R, g_R);
    cudaGetSymbolAddress((void**)&G, g_G);

    static bool attr_set = false;
    if (!attr_set) {
        cudaFuncSetAttribute(big_gemm, cudaFuncAttributeMaxDynamicSharedMemorySize, BIG_SMEM);
        attr_set = true;
    }

    const dim3 blk(NTHREADS);
    const dim3 ggrd(HF / BN, NN / BM);   // (4, 64)

    // prep: zero accumulators, then fused rna-convert + segment rowsums
    zero_buf<<<(GRAPHS * NN + 255) / 256, 256>>>(R, GRAPHS * NN);
    zero_buf<<<(GRAPHS * HF + 255) / 256, 256>>>(G, GRAPHS * HF);
    segrow_conv<<<dim3(NN / 1024, NN / SR_CHUNK), 256>>>(adj, seg, adjC, R);

    // layer 1
    gemm_small<true><<<ggrd, blk>>>(X, W1, bufA, NN, HF, 256);
    big_gemm<<<ggrd, blk, BIG_SMEM>>>(adjC, bufA, bufB, b1, 1);
    // layer 2
    gemm_small<true><<<ggrd, blk>>>(bufB, W2, bufA, NN, HF, HF);
    big_gemm<<<ggrd, blk, BIG_SMEM>>>(adjC, bufA, bufB, b2, 1);
    // layer 3 folded: hW3 (fp32), then R @ hW3
    gemm_small<false><<<ggrd, blk>>>(bufB, W3, bufA, NN, HF, HF);
    tiny_gemm<<<dim3(HF / 128, NN / 512), 256>>>(R, bufA, G);

    // tail
    mlp_tail<<<1, 1024>>>(G, seg, b3, D1, db1, D2, db2, D3, db3, out);
}

// round 8
// speedup vs baseline: 2.7696x; 1.6783x over previous
#include <cuda_runtime.h>
#include <cuda_bf16.h>
#include <cstdint>
#include <math.h>

// ---------------------------------------------------------------------------
// GCNGraph (sm_100, legacy mma.sync).
//   L1: h = relu(adj @ (X@W1) + b1)        big GEMM in BF16 (m16n8k16+ldmatrix)
//   L2: h = relu(adj @ (h@W2) + b2)        big GEMM in BF16
//   L3 folded: mean_s(adj@hW3+b3) = R@hW3/cnt+b3, fp32 path
//   MLP tail + sigmoid.
// R8: big GEMMs bf16 mma.sync m16n8k16, ldmatrix frag loads, bf16 adjacency.
// ---------------------------------------------------------------------------

#define NN      8192
#define HF      512
#define GRAPHS  64

__device__ __nv_bfloat16 g_adjB[(size_t)NN * NN];  // bf16 adjacency (128MB)
__device__ __nv_bfloat16 g_bufAb[NN * HF];         // h@W bf16 (layers 1-2)
__device__ float g_bufA[NN * HF];                  // h@W3 fp32 (layer 3)
__device__ float g_bufB[NN * HF];                  // layer output h
__device__ float g_R[GRAPHS * NN];                 // segment rowsums of adj
__device__ float g_G[GRAPHS * HF];                 // segment sums layer-3

__device__ __forceinline__ uint32_t f2tf32(float x) {
    uint32_t r;
    asm("cvt.rna.tf32.f32 %0, %1;" : "=r"(r) : "f"(x));
    return r;
}
__device__ __forceinline__ uint32_t smem_u32(const void* p) {
    uint32_t a;
    asm("{ .reg .u64 t; cvta.to.shared.u64 t, %1; cvt.u32.u64 %0, t; }" : "=r"(a) : "l"(p));
    return a;
}

// ===================== bf16 big GEMM (adj @ hW) =============================
// C[8192,512] = Abf[8192,8192] @ Bbf[8192,512] (+bias, relu), fp32 accum.

#define NSTG 4
#define BBM 128
#define BBN 128
#define BBK 32
#define A_RSTRIDE 80    // bytes per A smem row (64 data + 16 pad) conflict-free
#define B_RSTRIDE 272   // bytes per B smem row (256 data + 16 pad)
#define A_BYTES (BBM * A_RSTRIDE)        // 10240
#define B_BYTES (BBK * B_RSTRIDE)        // 8704
#define STAGE_BYTES (A_BYTES + B_BYTES)  // 18944
#define BIG_SMEM (NSTG * STAGE_BYTES)    // 75776

__device__ __forceinline__ void ldmA(uint32_t a[4], uint32_t addr) {
    asm volatile("ldmatrix.sync.aligned.m8n8.x4.shared.b16 {%0,%1,%2,%3}, [%4];"
                 : "=r"(a[0]), "=r"(a[1]), "=r"(a[2]), "=r"(a[3]) : "r"(addr));
}
__device__ __forceinline__ void ldmB(uint32_t b[2], uint32_t addr) {
    asm volatile("ldmatrix.sync.aligned.m8n8.x2.trans.shared.b16 {%0,%1}, [%2];"
                 : "=r"(b[0]), "=r"(b[1]) : "r"(addr));
}
__device__ __forceinline__ void mma_bf16(float* c, const uint32_t* a, const uint32_t* b) {
    asm volatile(
        "mma.sync.aligned.m16n8k16.row.col.f32.bf16.bf16.f32 "
        "{%0,%1,%2,%3}, {%4,%5,%6,%7}, {%8,%9}, {%0,%1,%2,%3};"
        : "+f"(c[0]), "+f"(c[1]), "+f"(c[2]), "+f"(c[3])
        : "r"(a[0]), "r"(a[1]), "r"(a[2]), "r"(a[3]), "r"(b[0]), "r"(b[1]));
}

__global__ void __launch_bounds__(256, 2)
big_gemm_bf16(const __nv_bfloat16* __restrict__ A, const __nv_bfloat16* __restrict__ B,
              float* __restrict__ C, const float* __restrict__ bias, int relu)
{
    extern __shared__ char smem[];
    const uint32_t sbase = smem_u32(smem);

    const int tid  = threadIdx.x;
    const int warp = tid >> 5;
    const int lane = tid & 31;
    const int bm = blockIdx.y * BBM;
    const int bn = blockIdx.x * BBN;
    const int wm = (warp >> 2) * 64;
    const int wn = (warp & 3) * 32;
    const int g  = lane >> 2;
    const int q  = lane & 3;
    const int nk = NN / BBK;   // 256

    float acc[4][4][4];
    #pragma unroll
    for (int i = 0; i < 4; i++)
        #pragma unroll
        for (int j = 0; j < 4; j++)
            #pragma unroll
            for (int r = 0; r < 4; r++) acc[i][j][r] = 0.f;

    // cp.async chunk mapping (16B chunks, 2 A + 2 B per thread per stage)
    auto issue = [&](int slot, int k0) {
        const uint32_t ab = sbase + slot * STAGE_BYTES;
        const uint32_t bb = ab + A_BYTES;
        #pragma unroll
        for (int p = 0; p < 2; p++) {
            const int ca = tid + 256 * p;
            const int arow = ca >> 2, acc_ = ca & 3;           // 128 rows x 4 chunks
            asm volatile("cp.async.cg.shared.global [%0], [%1], 16;" ::
                "r"(ab + (uint32_t)(arow * A_RSTRIDE + acc_ * 16)),
                "l"(A + (size_t)(bm + arow) * NN + k0 + acc_ * 8));
            const int cb = tid + 256 * p;
            const int brow = cb >> 4, bcc = cb & 15;           // 32 rows x 16 chunks
            asm volatile("cp.async.cg.shared.global [%0], [%1], 16;" ::
                "r"(bb + (uint32_t)(brow * B_RSTRIDE + bcc * 16)),
                "l"(B + (size_t)(k0 + brow) * HF + bn + bcc * 8));
        }
        asm volatile("cp.async.commit_group;" ::: "memory");
    };

    issue(0, 0);
    issue(1, BBK);
    issue(2, 2 * BBK);

    // ldmatrix per-lane address components (constant across t)
    const int a_lrow = lane & 15;            // row within 16-row frag
    const int a_lkb  = (lane >> 4) * 8;      // k col-block (0 or 8)
    const int b_lrow = lane & 15;            // k row within 16

    for (int t = 0; t < nk; t++) {
        asm volatile("cp.async.wait_group 2;" ::: "memory");
        __syncthreads();
        if (t + 3 < nk) issue((t + 3) & 3, (t + 3) * BBK);

        const uint32_t ab = sbase + (t & 3) * STAGE_BYTES;
        const uint32_t bb = ab + A_BYTES;

        #pragma unroll
        for (int kk = 0; kk < BBK; kk += 16) {
            uint32_t af[4][4], bf[4][2];
            #pragma unroll
            for (int i = 0; i < 4; i++)
                ldmA(af[i], ab + (uint32_t)((wm + i * 16 + a_lrow) * A_RSTRIDE
                                            + (kk + a_lkb) * 2));
            #pragma unroll
            for (int j = 0; j < 4; j++)
                ldmB(bf[j], bb + (uint32_t)((kk + b_lrow) * B_RSTRIDE
                                            + (wn + j * 8) * 2));
            #pragma unroll
            for (int i = 0; i < 4; i++)
                #pragma unroll
                for (int j = 0; j < 4; j++)
                    mma_bf16(acc[i][j], af[i], bf[j]);
        }
    }

    // epilogue: bias + relu -> fp32 C
    #pragma unroll
    for (int i = 0; i < 4; i++) {
        #pragma unroll
        for (int j = 0; j < 4; j++) {
            const int row = bm + wm + i * 16 + g;
            const int col = bn + wn + j * 8 + 2 * q;
            const float bv0 = bias[col], bv1 = bias[col + 1];
            float v0 = acc[i][j][0] + bv0;
            float v1 = acc[i][j][1] + bv1;
            float v2 = acc[i][j][2] + bv0;
            float v3 = acc[i][j][3] + bv1;
            if (relu) {
                v0 = fmaxf(v0, 0.f); v1 = fmaxf(v1, 0.f);
                v2 = fmaxf(v2, 0.f); v3 = fmaxf(v3, 0.f);
            }
            *(float2*)(C + (size_t)row * HF + col)       = make_float2(v0, v1);
            *(float2*)(C + (size_t)(row + 8) * HF + col) = make_float2(v2, v3);
        }
    }
}

// ================== small SIMT tf32 GEMM (H @ W) ===========================
// OUT=0: fp32 store (layer 3). OUT=1: bf16 store (layers 1-2 -> big gemm B).
__device__ __forceinline__ void mma_frag(float* c, const uint32_t* a, const uint32_t* b) {
    asm volatile(
        "mma.sync.aligned.m16n8k8.row.col.f32.tf32.tf32.f32 "
        "{%0,%1,%2,%3}, {%4,%5,%6,%7}, {%8,%9}, {%0,%1,%2,%3};"
        : "+f"(c[0]), "+f"(c[1]), "+f"(c[2]), "+f"(c[3])
        : "r"(a[0]), "r"(a[1]), "r"(a[2]), "r"(a[3]), "r"(b[0]), "r"(b[1]));
}

#define BM 128
#define BN 128
#define BK 16
#define NTHREADS 256

template <int OUT_BF16>
__global__ void __launch_bounds__(NTHREADS)
gemm_small(const float* __restrict__ A, const float* __restrict__ B,
           float* __restrict__ Cf, __nv_bfloat16* __restrict__ Cb,
           int M, int N, int K)
{
    __shared__ uint32_t As[2][BM][BK + 4];
    __shared__ uint32_t Bs[2][BK][BN + 8];

    const int bm = blockIdx.y * BM;
    const int bn = blockIdx.x * BN;
    const int tid  = threadIdx.x;
    const int warp = tid >> 5;
    const int lane = tid & 31;
    const int wm = (warp >> 2) * 64;
    const int wn = (warp & 3) * 32;
    const int g  = lane >> 2;
    const int q  = lane & 3;

    float acc[4][4][4];
    #pragma unroll
    for (int i = 0; i < 4; i++)
        #pragma unroll
        for (int j = 0; j < 4; j++)
            #pragma unroll
            for (int r = 0; r < 4; r++) acc[i][j][r] = 0.f;

    const int arow = tid >> 2;
    const int acol = (tid & 3) * 4;
    const int brow = tid >> 5;
    const int bcol = (tid & 31) * 4;
    const int nk = K / BK;

    float4 ra0, ra1, rb0, rb1;
    ra0 = *(const float4*)(A + (size_t)(bm + arow) * K + acol);
    ra1 = *(const float4*)(A + (size_t)(bm + arow + 64) * K + acol);
    rb0 = *(const float4*)(B + (size_t)(brow) * N + bn + bcol);
    rb1 = *(const float4*)(B + (size_t)(brow + 8) * N + bn + bcol);
    {
        uint4 u;
        u.x = f2tf32(ra0.x); u.y = f2tf32(ra0.y); u.z = f2tf32(ra0.z); u.w = f2tf32(ra0.w);
        *(uint4*)&As[0][arow][acol] = u;
        u.x = f2tf32(ra1.x); u.y = f2tf32(ra1.y); u.z = f2tf32(ra1.z); u.w = f2tf32(ra1.w);
        *(uint4*)&As[0][arow + 64][acol] = u;
        u.x = f2tf32(rb0.x); u.y = f2tf32(rb0.y); u.z = f2tf32(rb0.z); u.w = f2tf32(rb0.w);
        *(uint4*)&Bs[0][brow][bcol] = u;
        u.x = f2tf32(rb1.x); u.y = f2tf32(rb1.y); u.z = f2tf32(rb1.z); u.w = f2tf32(rb1.w);
        *(uint4*)&Bs[0][brow + 8][bcol] = u;
    }
    __syncthreads();

    for (int t = 0; t < nk; t++) {
        const int cur = t & 1;
        const int nxt = cur ^ 1;
        const bool more = (t + 1 < nk);
        if (more) {
            const int k0 = (t + 1) * BK;
            ra0 = *(const float4*)(A + (size_t)(bm + arow) * K + k0 + acol);
            ra1 = *(const float4*)(A + (size_t)(bm + arow + 64) * K + k0 + acol);
            rb0 = *(const float4*)(B + (size_t)(k0 + brow) * N + bn + bcol);
            rb1 = *(const float4*)(B + (size_t)(k0 + brow + 8) * N + bn + bcol);
        }
        #pragma unroll
        for (int kk = 0; kk < BK; kk += 8) {
            uint32_t af[4][4], bf[4][2];
            #pragma unroll
            for (int i = 0; i < 4; i++) {
                const int r0 = wm + i * 16 + g;
                af[i][0] = As[cur][r0][kk + q];
                af[i][1] = As[cur][r0 + 8][kk + q];
                af[i][2] = As[cur][r0][kk + q + 4];
                af[i][3] = As[cur][r0 + 8][kk + q + 4];
            }
            #pragma unroll
            for (int j = 0; j < 4; j++) {
                const int c0 = wn + j * 8 + g;
                bf[j][0] = Bs[cur][kk + q][c0];
                bf[j][1] = Bs[cur][kk + q + 4][c0];
            }
            #pragma unroll
            for (int i = 0; i < 4; i++)
                #pragma unroll
                for (int j = 0; j < 4; j++)
                    mma_frag(acc[i][j], af[i], bf[j]);
        }
        if (more) {
            uint4 u;
            u.x = f2tf32(ra0.x); u.y = f2tf32(ra0.y); u.z = f2tf32(ra0.z); u.w = f2tf32(ra0.w);
            *(uint4*)&As[nxt][arow][acol] = u;
            u.x = f2tf32(ra1.x); u.y = f2tf32(ra1.y); u.z = f2tf32(ra1.z); u.w = f2tf32(ra1.w);
            *(uint4*)&As[nxt][arow + 64][acol] = u;
            u.x = f2tf32(rb0.x); u.y = f2tf32(rb0.y); u.z = f2tf32(rb0.z); u.w = f2tf32(rb0.w);
            *(uint4*)&Bs[nxt][brow][bcol] = u;
            u.x = f2tf32(rb1.x); u.y = f2tf32(rb1.y); u.z = f2tf32(rb1.z); u.w = f2tf32(rb1.w);
            *(uint4*)&Bs[nxt][brow + 8][bcol] = u;
        }
        __syncthreads();
    }

    #pragma unroll
    for (int i = 0; i < 4; i++) {
        #pragma unroll
        for (int j = 0; j < 4; j++) {
            const int row = bm + wm + i * 16 + g;
            const int col = bn + wn + j * 8 + 2 * q;
            if (OUT_BF16) {
                *(__nv_bfloat162*)(Cb + (size_t)row * N + col) =
                    __floats2bfloat162_rn(acc[i][j][0], acc[i][j][1]);
                *(__nv_bfloat162*)(Cb + (size_t)(row + 8) * N + col) =
                    __floats2bfloat162_rn(acc[i][j][2], acc[i][j][3]);
            } else {
                *(float2*)(Cf + (size_t)row * N + col) =
                    make_float2(acc[i][j][0], acc[i][j][1]);
                *(float2*)(Cf + (size_t)(row + 8) * N + col) =
                    make_float2(acc[i][j][2], acc[i][j][3]);
            }
        }
    }
}

// =============================== helpers ====================================

// Fused: adjB = bf16(adj) AND R[s][col] += segment rowsums (fp32).
#define SR_CHUNK 256

__global__ void __launch_bounds__(256)
segrow_conv(const float* __restrict__ adj, const int* __restrict__ seg,
            __nv_bfloat16* __restrict__ adjB, float* __restrict__ R)
{
    const int col = (blockIdx.x * 256 + threadIdx.x) * 4;
    const int r0  = blockIdx.y * SR_CHUNK;
    const int r1  = r0 + SR_CHUNK;

    float4 acc = make_float4(0.f, 0.f, 0.f, 0.f);
    int cur = seg[r0];

    #pragma unroll 4
    for (int i = r0; i < r1; i++) {
        const int s = __ldg(&seg[i]);
        if (s != cur) {
            atomicAdd(&R[(size_t)cur * NN + col],     acc.x);
            atomicAdd(&R[(size_t)cur * NN + col + 1], acc.y);
            atomicAdd(&R[(size_t)cur * NN + col + 2], acc.z);
            atomicAdd(&R[(size_t)cur * NN + col + 3], acc.w);
            acc = make_float4(0.f, 0.f, 0.f, 0.f);
            cur = s;
        }
        const float4 v = *(const float4*)(adj + (size_t)i * NN + col);
        acc.x += v.x; acc.y += v.y; acc.z += v.z; acc.w += v.w;
        __nv_bfloat162 o01 = __floats2bfloat162_rn(v.x, v.y);
        __nv_bfloat162 o23 = __floats2bfloat162_rn(v.z, v.w);
        uint2 o;
        o.x = *(uint32_t*)&o01;
        o.y = *(uint32_t*)&o23;
        *(uint2*)(adjB + (size_t)i * NN + col) = o;
    }
    atomicAdd(&R[(size_t)cur * NN + col],     acc.x);
    atomicAdd(&R[(size_t)cur * NN + col + 1], acc.y);
    atomicAdd(&R[(size_t)cur * NN + col + 2], acc.z);
    atomicAdd(&R[(size_t)cur * NN + col + 3], acc.w);
}

__global__ void zero_buf(float* __restrict__ p, int n) {
    const int i = blockIdx.x * blockDim.x + threadIdx.x;
    if (i < n) p[i] = 0.f;
}

// G[64,512] += R[64,8192] @ H[8192,512]  (fp32 SIMT, k-split with atomics)
__global__ void __launch_bounds__(256)
tiny_gemm(const float* __restrict__ R, const float* __restrict__ H,
          float* __restrict__ G)
{
    __shared__ float sA[64][33];
    __shared__ float sB[32][132];
    const int tid = threadIdx.x;
    const int bn = blockIdx.x * 128;
    const int k0 = blockIdx.y * 512;
    const int row0 = (tid >> 5) * 8;
    const int col0 = (tid & 31) * 4;

    float acc[8][4];
    #pragma unroll
    for (int r = 0; r < 8; r++)
        #pragma unroll
        for (int c = 0; c < 4; c++) acc[r][c] = 0.f;

    for (int kt = 0; kt < 512; kt += 32) {
        const int k = k0 + kt;
        #pragma unroll
        for (int i = 0; i < 8; i++) {
            const int e = tid + 256 * i;
            sA[e >> 5][e & 31] = R[(size_t)(e >> 5) * NN + k + (e & 31)];
        }
        #pragma unroll
        for (int i = 0; i < 16; i++) {
            const int e = tid + 256 * i;
            sB[e >> 7][e & 127] = H[(size_t)(k + (e >> 7)) * HF + bn + (e & 127)];
        }
        __syncthreads();
        #pragma unroll
        for (int kk = 0; kk < 32; kk++) {
            const float4 b4 = *(const float4*)&sB[kk][col0];
            #pragma unroll
            for (int r = 0; r < 8; r++) {
                const float a = sA[row0 + r][kk];
                acc[r][0] += a * b4.x;
                acc[r][1] += a * b4.y;
                acc[r][2] += a * b4.z;
                acc[r][3] += a * b4.w;
            }
        }
        __syncthreads();
    }
    #pragma unroll
    for (int r = 0; r < 8; r++)
        #pragma unroll
        for (int c = 0; c < 4; c++)
            atomicAdd(&G[(row0 + r) * HF + bn + col0 + c], acc[r][c]);
}

// mean + b3 + MLP (512->16->8->1) + sigmoid. one block, 1024 threads.
__global__ void mlp_tail(const float* __restrict__ G, const int* __restrict__ seg,
                         const float* __restrict__ b3,
                         const float* __restrict__ D1, const float* __restrict__ db1,
                         const float* __restrict__ D2, const float* __restrict__ db2,
                         const float* __restrict__ D3, const float* __restrict__ db3,
                         float* __restrict__ out)
{
    __shared__ int   cnt[GRAPHS];
    __shared__ float s1[GRAPHS][16];
    __shared__ float s2[GRAPHS][8];
    const int tid = threadIdx.x;

    if (tid < GRAPHS) cnt[tid] = 0;
    __syncthreads();
    for (int n = tid; n < NN; n += 1024) atomicAdd(&cnt[seg[n]], 1);
    __syncthreads();

    {
        const int gph = tid >> 4, j = tid & 15;
        const float inv = 1.f / (float)max(cnt[gph], 1);
        float acc = 0.f;
        const float* grow = G + gph * HF;
        for (int k = 0; k < HF; k++)
            acc += (grow[k] * inv + b3[k]) * D1[k * 16 + j];
        s1[gph][j] = fmaxf(acc + db1[j], 0.f);
    }
    __syncthreads();
    if (tid < 512) {
        const int gph = tid >> 3, j = tid & 7;
        float acc = 0.f;
        for (int k = 0; k < 16; k++) acc += s1[gph][k] * D2[k * 8 + j];
        s2[gph][j] = fmaxf(acc + db2[j], 0.f);
    }
    __syncthreads();
    if (tid < GRAPHS) {
        float acc = 0.f;
        for (int k = 0; k < 8; k++) acc += s2[tid][k] * D3[k];
        out[tid] = 1.f / (1.f + expf(-(acc + db3[0])));
    }
}

// ================================= host =====================================

extern "C" void kernel_launch(void* const* d_in, const int* in_sizes, int n_in,
                              void* d_out, int out_size)
{
    const float* X   = (const float*)d_in[0];
    const float* adj = (const float*)d_in[1];
    const int*   seg = (const int*)d_in[2];
    const int base = n_in - 12;
    const float* W1  = (const float*)d_in[base + 0];
    const float* b1  = (const float*)d_in[base + 1];
    const float* W2  = (const float*)d_in[base + 2];
    const float* b2  = (const float*)d_in[base + 3];
    const float* W3  = (const float*)d_in[base + 4];
    const float* b3  = (const float*)d_in[base + 5];
    const float* D1  = (const float*)d_in[base + 6];
    const float* db1 = (const float*)d_in[base + 7];
    const float* D2  = (const float*)d_in[base + 8];
    const float* db2 = (const float*)d_in[base + 9];
    const float* D3  = (const float*)d_in[base + 10];
    const float* db3 = (const float*)d_in[base + 11];
    float* out = (float*)d_out;

    __nv_bfloat16 *adjB, *bufAb;
    float *bufA, *bufB, *R, *G;
    cudaGetSymbolAddress((void**)&adjB, g_adjB);
    cudaGetSymbolAddress((void**)&bufAb, g_bufAb);
    cudaGetSymbolAddress((void**)&bufA, g_bufA);
    cudaGetSymbolAddress((void**)&bufB, g_bufB);
    cudaGetSymbolAddress((void**)&R, g_R);
    cudaGetSymbolAddress((void**)&G, g_G);

    static bool attr_set = false;
    if (!attr_set) {
        cudaFuncSetAttribute(big_gemm_bf16, cudaFuncAttributeMaxDynamicSharedMemorySize, BIG_SMEM);
        attr_set = true;
    }

    const dim3 blk(NTHREADS);
    const dim3 ggrd(HF / BN, NN / BM);   // (4, 64)

    // prep
    zero_buf<<<(GRAPHS * NN + 255) / 256, 256>>>(R, GRAPHS * NN);
    zero_buf<<<(GRAPHS * HF + 255) / 256, 256>>>(G, GRAPHS * HF);
    segrow_conv<<<dim3(NN / 1024, NN / SR_CHUNK), 256>>>(adj, seg, adjB, R);

    // layer 1
    gemm_small<1><<<ggrd, blk>>>(X, W1, nullptr, bufAb, NN, HF, 256);
    big_gemm_bf16<<<ggrd, blk, BIG_SMEM>>>(adjB, bufAb, bufB, b1, 1);
    // layer 2
    gemm_small<1><<<ggrd, blk>>>(bufB, W2, nullptr, bufAb, NN, HF, HF);
    big_gemm_bf16<<<ggrd, blk, BIG_SMEM>>>(adjB, bufAb, bufB, b2, 1);
    // layer 3 folded: hW3 (fp32), then R @ hW3
    gemm_small<0><<<ggrd, blk>>>(bufB, W3, bufA, nullptr, NN, HF, HF);
    tiny_gemm<<<dim3(HF / 128, NN / 512), 256>>>(R, bufA, G);

    // tail
    mlp_tail<<<1, 1024>>>(G, seg, b3, D1, db1, D2, db2, D3, db3, out);
}